// round 7
// baseline (speedup 1.0000x reference)
#include <cuda_runtime.h>
#include <cuda_bf16.h>
#include <math.h>

#define SEQ 2048
#define HIDDIM 768
#define NQH 12
#define NKVH 3
#define HDIM 64
#define QKVC 1152        // (12 + 3 + 3) * 64
#define NEXP 16
#define FFD 1536
#define NROWS (SEQ * 2)  // top-2 assignments

// ---------------- f32x2 packed-math helpers (SASS FFMA2 / FMUL2) ----------------
__device__ __forceinline__ unsigned long long pk2(float x, float y) {
    unsigned long long r;
    asm("mov.b64 %0, {%1, %2};" : "=l"(r) : "f"(x), "f"(y));
    return r;
}
__device__ __forceinline__ float2 upk2(unsigned long long p) {
    float2 f;
    asm("mov.b64 {%0, %1}, %2;" : "=f"(f.x), "=f"(f.y) : "l"(p));
    return f;
}
__device__ __forceinline__ void fma2(unsigned long long& d, unsigned long long a, unsigned long long b) {
    asm("fma.rn.f32x2 %0, %1, %2, %0;" : "+l"(d) : "l"(a), "l"(b));
}
__device__ __forceinline__ unsigned long long mul2(unsigned long long a, unsigned long long b) {
    unsigned long long r;
    asm("mul.rn.f32x2 %0, %1, %2;" : "=l"(r) : "l"(a), "l"(b));
    return r;
}

// ---------------- device-global scratch ----------------
__device__ float g_xn [SEQ * HIDDIM];
__device__ float g_qkv[SEQ * QKVC];
__device__ float g_att[SEQ * HIDDIM];
__device__ float g_h  [SEQ * HIDDIM];
__device__ float g_mi [SEQ * HIDDIM];
__device__ int   g_eidx[SEQ * 2];
__device__ float g_ew  [SEQ * 2];
__device__ int   g_cnt[NEXP];
__device__ int   g_off[NEXP + 1];
__device__ int   g_cur[NEXP];
__device__ int   g_rows_tok[NROWS];
__device__ float g_rows_w [NROWS];
__device__ int   g_tok_row[SEQ * 2];
__device__ float g_hid[(size_t)NROWS * FFD];
__device__ float g_yex[(size_t)NROWS * HIDDIM];

// ---------------- RMSNorm ----------------
__global__ void rmsnorm_kernel(const float* __restrict__ x, const float* __restrict__ w,
                               float* __restrict__ out) {
    int t = blockIdx.x;
    __shared__ float red[256];
    const float* xr = x + (size_t)t * HIDDIM;
    float ss = 0.f;
    for (int i = threadIdx.x; i < HIDDIM; i += 256) { float v = xr[i]; ss += v * v; }
    red[threadIdx.x] = ss;
    __syncthreads();
    for (int s2 = 128; s2 > 0; s2 >>= 1) {
        if (threadIdx.x < s2) red[threadIdx.x] += red[threadIdx.x + s2];
        __syncthreads();
    }
    float inv = rsqrtf(red[0] * (1.0f / HIDDIM) + 1e-6f);
    for (int i = threadIdx.x; i < HIDDIM; i += 256)
        out[(size_t)t * HIDDIM + i] = xr[i] * inv * w[i];
}

// ---------------- 128x64 GEMM with f32x2 (optionally + residual) ----------------
// M must be a multiple of 128, N multiple of 64, K multiple of 16.
template <bool ADD_RES>
__global__ __launch_bounds__(256) void gemm_f2(const float* __restrict__ A,
                                               const float* __restrict__ B,
                                               const float* __restrict__ Res,
                                               float* __restrict__ C,
                                               int M, int N, int K) {
    __shared__ unsigned long long As2[16][128];  // (a,a) duplicated pairs, k-major
    __shared__ float Bs[16][64];

    const int m0 = blockIdx.y * 128, n0 = blockIdx.x * 64;
    const int tid = threadIdx.x;

    const int ar = tid >> 1;              // 0..127 A row within tile
    const int ak = (tid & 1) * 8;         // 0 or 8
    const int bk = tid >> 4;              // 0..15
    const int bn = (tid & 15) * 4;        // 0..60
    const int tr = (tid >> 3) * 4;        // row base 0..124
    const int tc = (tid & 7) * 8;         // col base 0..56

    const float* Aptr = A + (size_t)(m0 + ar) * K + ak;
    const float* Bptr = B + (size_t)bk * N + n0 + bn;

    unsigned long long acc[4][4];
#pragma unroll
    for (int i = 0; i < 4; i++)
#pragma unroll
        for (int j = 0; j < 4; j++) acc[i][j] = 0ull;

    for (int k0 = 0; k0 < K; k0 += 16) {
        float4 a0 = *(const float4*)(Aptr + k0);
        float4 a1 = *(const float4*)(Aptr + k0 + 4);
        As2[ak + 0][ar] = pk2(a0.x, a0.x);
        As2[ak + 1][ar] = pk2(a0.y, a0.y);
        As2[ak + 2][ar] = pk2(a0.z, a0.z);
        As2[ak + 3][ar] = pk2(a0.w, a0.w);
        As2[ak + 4][ar] = pk2(a1.x, a1.x);
        As2[ak + 5][ar] = pk2(a1.y, a1.y);
        As2[ak + 6][ar] = pk2(a1.z, a1.z);
        As2[ak + 7][ar] = pk2(a1.w, a1.w);
        *(float4*)&Bs[bk][bn] = *(const float4*)(Bptr + (size_t)k0 * N);
        __syncthreads();
#pragma unroll
        for (int k = 0; k < 16; k++) {
            ulonglong2 a01 = *(const ulonglong2*)&As2[k][tr];
            ulonglong2 a23 = *(const ulonglong2*)&As2[k][tr + 2];
            const ulonglong2* bp = (const ulonglong2*)&Bs[k][tc];
            ulonglong2 b01 = bp[0], b23 = bp[1];
            fma2(acc[0][0], a01.x, b01.x); fma2(acc[0][1], a01.x, b01.y);
            fma2(acc[0][2], a01.x, b23.x); fma2(acc[0][3], a01.x, b23.y);
            fma2(acc[1][0], a01.y, b01.x); fma2(acc[1][1], a01.y, b01.y);
            fma2(acc[1][2], a01.y, b23.x); fma2(acc[1][3], a01.y, b23.y);
            fma2(acc[2][0], a23.x, b01.x); fma2(acc[2][1], a23.x, b01.y);
            fma2(acc[2][2], a23.x, b23.x); fma2(acc[2][3], a23.x, b23.y);
            fma2(acc[3][0], a23.y, b01.x); fma2(acc[3][1], a23.y, b01.y);
            fma2(acc[3][2], a23.y, b23.x); fma2(acc[3][3], a23.y, b23.y);
        }
        __syncthreads();
    }
#pragma unroll
    for (int i = 0; i < 4; i++) {
        int row = m0 + tr + i;
        float2 u0 = upk2(acc[i][0]), u1 = upk2(acc[i][1]);
        float2 u2 = upk2(acc[i][2]), u3 = upk2(acc[i][3]);
        float4 v0 = make_float4(u0.x, u0.y, u1.x, u1.y);
        float4 v1 = make_float4(u2.x, u2.y, u3.x, u3.y);
        if (ADD_RES) {
            float4 r0 = *(const float4*)&Res[(size_t)row * N + n0 + tc];
            float4 r1 = *(const float4*)&Res[(size_t)row * N + n0 + tc + 4];
            v0.x += r0.x; v0.y += r0.y; v0.z += r0.z; v0.w += r0.w;
            v1.x += r1.x; v1.y += r1.y; v1.z += r1.z; v1.w += r1.w;
        }
        *(float4*)&C[(size_t)row * N + n0 + tc] = v0;
        *(float4*)&C[(size_t)row * N + n0 + tc + 4] = v1;
    }
}

// ---------------- RoPE ----------------
__global__ void rope_kernel(float* __restrict__ qkv) {
    int s = blockIdx.x;
    int t = threadIdx.x;
    if (t >= (NQH + NKVH) * (HDIM / 2)) return;
    int hh = t / 32, p = t & 31;
    int col = (hh < NQH) ? hh * HDIM : (NQH * HDIM + (hh - NQH) * HDIM);
    float expo = (float)(2 * p) * (1.0f / HDIM);
    float inv = powf(10000.0f, -expo);
    float ang = (float)s * inv;
    float c, sn;
    sincosf(ang, &sn, &c);
    float* base = qkv + (size_t)s * QKVC + col;
    float x0 = base[2 * p], x1 = base[2 * p + 1];
    base[2 * p]     = x0 * c - x1 * sn;
    base[2 * p + 1] = x0 * sn + x1 * c;
}

// ---------------- causal flash attention (fp32, f32x2 inner loops) ----------------
__global__ __launch_bounds__(256) void attn_kernel(const float* __restrict__ qkv,
                                                   float* __restrict__ out) {
    extern __shared__ float sm[];
    float* QsT  = sm;                  // [64][68]
    float* Kst  = QsT + 64 * 68;       // [64][68]
    float* Vs   = Kst + 64 * 68;       // [64][64]
    float* Ss   = Vs + 64 * 64;        // [64][68]
    float* rowM = Ss + 64 * 68;
    float* rowL = rowM + 64;
    float* partM = rowL + 64;          // [4][64]
    float* partL = partM + 256;        // [4][64]

    const int h = blockIdx.y, kvh = h >> 2;
    const int qt = gridDim.x - 1 - blockIdx.x;   // heavy tiles first
    const int q0 = qt * 64;
    const int tid = threadIdx.x;
    const int r = tid & 63;
    const int cg = tid >> 6;

    unsigned long long op[8];
#pragma unroll
    for (int j = 0; j < 8; j++) op[j] = 0ull;

    for (int i = tid; i < 4096; i += 256) {
        int m = i >> 6, d = i & 63;
        QsT[d * 68 + m] = qkv[(size_t)(q0 + m) * QKVC + h * HDIM + d] * 0.125f;
    }
    if (tid < 64) { rowM[tid] = -1e30f; rowL[tid] = 0.f; }
    __syncthreads();

    for (int kt = 0; kt <= qt; ++kt) {
        const int k0 = kt * 64;
        for (int i = tid; i < 4096; i += 256) {
            int c = i >> 6, d = i & 63;
            const float* row = qkv + (size_t)(k0 + c) * QKVC;
            Kst[d * 68 + c] = row[NQH * HDIM + kvh * HDIM + d];
            Vs[c * 64 + d]  = row[(NQH + NKVH) * HDIM + kvh * HDIM + d];
        }
        __syncthreads();

        unsigned long long sp[8];
#pragma unroll
        for (int j = 0; j < 8; j++) sp[j] = 0ull;
#pragma unroll 4
        for (int d = 0; d < 64; ++d) {
            unsigned long long qq;
            {
                float qv = QsT[d * 68 + r];
                qq = pk2(qv, qv);
            }
            const ulonglong2* kp = (const ulonglong2*)&Kst[d * 68 + cg * 16];
            ulonglong2 ka = kp[0], kb = kp[1], kc = kp[2], kd = kp[3];
            fma2(sp[0], qq, ka.x); fma2(sp[1], qq, ka.y);
            fma2(sp[2], qq, kb.x); fma2(sp[3], qq, kb.y);
            fma2(sp[4], qq, kc.x); fma2(sp[5], qq, kc.y);
            fma2(sp[6], qq, kd.x); fma2(sp[7], qq, kd.y);
        }

        float s[16];
#pragma unroll
        for (int j = 0; j < 8; j++) {
            float2 u = upk2(sp[j]);
            s[2 * j] = u.x; s[2 * j + 1] = u.y;
        }

        bool diag = (kt == qt);
        float lmax = -1e30f;
#pragma unroll
        for (int j = 0; j < 16; j++) {
            int c = cg * 16 + j;
            if (diag && (k0 + c > q0 + r)) s[j] = -1e30f;
            lmax = fmaxf(lmax, s[j]);
        }
        partM[cg * 64 + r] = lmax;
        __syncthreads();

        float m_old = rowM[r];
        float m_new = fmaxf(m_old,
                      fmaxf(fmaxf(partM[r], partM[64 + r]),
                            fmaxf(partM[128 + r], partM[192 + r])));
        float alpha = __expf(m_old - m_new);
        float lsum = 0.f;
#pragma unroll
        for (int j = 0; j < 16; j++) {
            float p = __expf(s[j] - m_new);
            Ss[r * 68 + cg * 16 + j] = p;
            lsum += p;
        }
        partL[cg * 64 + r] = lsum;
        {
            unsigned long long aa = pk2(alpha, alpha);
#pragma unroll
            for (int j = 0; j < 8; j++) op[j] = mul2(op[j], aa);
        }
        __syncthreads();

        if (cg == 0) {
            rowM[r] = m_new;
            rowL[r] = rowL[r] * alpha + partL[r] + partL[64 + r] + partL[128 + r] + partL[192 + r];
        }

#pragma unroll 4
        for (int c = 0; c < 64; c++) {
            unsigned long long pp;
            {
                float pv = Ss[r * 68 + c];
                pp = pk2(pv, pv);
            }
            const ulonglong2* vp = (const ulonglong2*)&Vs[c * 64 + cg * 16];
            ulonglong2 va = vp[0], vb = vp[1], vc = vp[2], vd = vp[3];
            fma2(op[0], pp, va.x); fma2(op[1], pp, va.y);
            fma2(op[2], pp, vb.x); fma2(op[3], pp, vb.y);
            fma2(op[4], pp, vc.x); fma2(op[5], pp, vc.y);
            fma2(op[6], pp, vd.x); fma2(op[7], pp, vd.y);
        }
        __syncthreads();
    }

    float inv = 1.f / rowL[r];
    float* orow = out + (size_t)(q0 + r) * (NQH * HDIM) + h * HDIM + cg * 16;
#pragma unroll
    for (int j = 0; j < 8; j++) {
        float2 u = upk2(op[j]);
        orow[2 * j]     = u.x * inv;
        orow[2 * j + 1] = u.y * inv;
    }
}

// ---------------- router ----------------
__global__ void router_kernel(const float* __restrict__ x, const float* __restrict__ wr) {
    int t = blockIdx.x;
    __shared__ float xr[HIDDIM];
    __shared__ float lg[NEXP];
    for (int i = threadIdx.x; i < HIDDIM; i += blockDim.x) xr[i] = x[(size_t)t * HIDDIM + i];
    __syncthreads();
    if (threadIdx.x < NEXP) {
        float a = 0.f;
        for (int k = 0; k < HIDDIM; k++) a += xr[k] * wr[k * NEXP + threadIdx.x];
        lg[threadIdx.x] = a;
    }
    __syncthreads();
    if (threadIdx.x == 0) {
        int i0 = 0; float l0 = lg[0];
        for (int e = 1; e < NEXP; e++) if (lg[e] > l0) { l0 = lg[e]; i0 = e; }
        int i1 = (i0 == 0) ? 1 : 0; float l1 = lg[i1];
        for (int e = 0; e < NEXP; e++) if (e != i0 && lg[e] > l1) { l1 = lg[e]; i1 = e; }
        float w0 = 1.f / (1.f + __expf(l1 - l0));
        g_eidx[2 * t] = i0; g_eidx[2 * t + 1] = i1;
        g_ew[2 * t] = w0;   g_ew[2 * t + 1] = 1.f - w0;
        atomicAdd(&g_cnt[i0], 1);
        atomicAdd(&g_cnt[i1], 1);
    }
}

__global__ void zero_cnt_kernel() { if (threadIdx.x < NEXP) g_cnt[threadIdx.x] = 0; }

__global__ void prefix_kernel() {
    if (threadIdx.x == 0) {
        int acc = 0;
        for (int e = 0; e < NEXP; e++) { g_off[e] = acc; g_cur[e] = acc; acc += g_cnt[e]; }
        g_off[NEXP] = acc;
    }
}

__global__ void scatter_kernel() {
    int t = blockIdx.x * blockDim.x + threadIdx.x;
    if (t >= SEQ) return;
    for (int j = 0; j < 2; j++) {
        int e = g_eidx[2 * t + j];
        int pos = atomicAdd(&g_cur[e], 1);
        g_rows_tok[pos] = t;
        g_rows_w[pos] = g_ew[2 * t + j];
        g_tok_row[2 * t + j] = pos;
    }
}

// ---------------- MoE GEMM1 (128x64 tiles, f32x2, gathered rows, fused SiLU) ----------------
__global__ __launch_bounds__(256) void moe_gemm1(const float* __restrict__ x,
                                                 const float* __restrict__ wgu) {
    const int e = blockIdx.z;
    const int off = g_off[e];
    const int cnt = g_off[e + 1] - off;
    const int m0 = blockIdx.y * 128;
    if (m0 >= cnt) return;
    const int n0 = blockIdx.x * 64;

    __shared__ unsigned long long As2[16][128];
    __shared__ float Bg[16][64];
    __shared__ float Bu[16][64];
    __shared__ int toks[128];

    const int tid = threadIdx.x;
    if (tid < 128) {
        int rr = m0 + tid;
        toks[tid] = (rr < cnt) ? g_rows_tok[off + rr] : g_rows_tok[off];
    }
    __syncthreads();

    const int ar = tid >> 1, ak = (tid & 1) * 8;
    const int bk = tid >> 4, bn = (tid & 15) * 4;
    const int tr = (tid >> 3) * 4, tc = (tid & 7) * 8;

    const float* Aptr = x + (size_t)toks[ar] * HIDDIM + ak;
    const float* Wb = wgu + (size_t)e * HIDDIM * (2 * FFD) + (size_t)bk * (2 * FFD) + n0 + bn;

    unsigned long long ag[4][4], au[4][4];
#pragma unroll
    for (int i = 0; i < 4; i++)
#pragma unroll
        for (int j = 0; j < 4; j++) { ag[i][j] = 0ull; au[i][j] = 0ull; }

    for (int k0 = 0; k0 < HIDDIM; k0 += 16) {
        float4 a0 = *(const float4*)(Aptr + k0);
        float4 a1 = *(const float4*)(Aptr + k0 + 4);
        As2[ak + 0][ar] = pk2(a0.x, a0.x);
        As2[ak + 1][ar] = pk2(a0.y, a0.y);
        As2[ak + 2][ar] = pk2(a0.z, a0.z);
        As2[ak + 3][ar] = pk2(a0.w, a0.w);
        As2[ak + 4][ar] = pk2(a1.x, a1.x);
        As2[ak + 5][ar] = pk2(a1.y, a1.y);
        As2[ak + 6][ar] = pk2(a1.z, a1.z);
        As2[ak + 7][ar] = pk2(a1.w, a1.w);
        const float* wrow = Wb + (size_t)k0 * (2 * FFD);
        *(float4*)&Bg[bk][bn] = *(const float4*)(wrow);
        *(float4*)&Bu[bk][bn] = *(const float4*)(wrow + FFD);
        __syncthreads();
#pragma unroll
        for (int k = 0; k < 16; k++) {
            ulonglong2 a01 = *(const ulonglong2*)&As2[k][tr];
            ulonglong2 a23 = *(const ulonglong2*)&As2[k][tr + 2];
            const ulonglong2* gp = (const ulonglong2*)&Bg[k][tc];
            const ulonglong2* up = (const ulonglong2*)&Bu[k][tc];
            ulonglong2 g01 = gp[0], g23 = gp[1];
            ulonglong2 u01 = up[0], u23 = up[1];
            fma2(ag[0][0], a01.x, g01.x); fma2(ag[0][1], a01.x, g01.y);
            fma2(ag[0][2], a01.x, g23.x); fma2(ag[0][3], a01.x, g23.y);
            fma2(ag[1][0], a01.y, g01.x); fma2(ag[1][1], a01.y, g01.y);
            fma2(ag[1][2], a01.y, g23.x); fma2(ag[1][3], a01.y, g23.y);
            fma2(ag[2][0], a23.x, g01.x); fma2(ag[2][1], a23.x, g01.y);
            fma2(ag[2][2], a23.x, g23.x); fma2(ag[2][3], a23.x, g23.y);
            fma2(ag[3][0], a23.y, g01.x); fma2(ag[3][1], a23.y, g01.y);
            fma2(ag[3][2], a23.y, g23.x); fma2(ag[3][3], a23.y, g23.y);
            fma2(au[0][0], a01.x, u01.x); fma2(au[0][1], a01.x, u01.y);
            fma2(au[0][2], a01.x, u23.x); fma2(au[0][3], a01.x, u23.y);
            fma2(au[1][0], a01.y, u01.x); fma2(au[1][1], a01.y, u01.y);
            fma2(au[1][2], a01.y, u23.x); fma2(au[1][3], a01.y, u23.y);
            fma2(au[2][0], a23.x, u01.x); fma2(au[2][1], a23.x, u01.y);
            fma2(au[2][2], a23.x, u23.x); fma2(au[2][3], a23.x, u23.y);
            fma2(au[3][0], a23.y, u01.x); fma2(au[3][1], a23.y, u01.y);
            fma2(au[3][2], a23.y, u23.x); fma2(au[3][3], a23.y, u23.y);
        }
        __syncthreads();
    }
#pragma unroll
    for (int i = 0; i < 4; i++) {
        int rr = m0 + tr + i;
        if (rr >= cnt) continue;
        float gg[8], uu[8];
#pragma unroll
        for (int j = 0; j < 4; j++) {
            float2 gv = upk2(ag[i][j]); gg[2 * j] = gv.x; gg[2 * j + 1] = gv.y;
            float2 uv = upk2(au[i][j]); uu[2 * j] = uv.x; uu[2 * j + 1] = uv.y;
        }
        float o[8];
#pragma unroll
        for (int j = 0; j < 8; j++) o[j] = gg[j] / (1.f + __expf(-gg[j])) * uu[j];
        float* dst = &g_hid[(size_t)(off + rr) * FFD + n0 + tc];
        *(float4*)dst = make_float4(o[0], o[1], o[2], o[3]);
        *(float4*)(dst + 4) = make_float4(o[4], o[5], o[6], o[7]);
    }
}

// ---------------- MoE GEMM2 (128x64 tiles, f32x2, combine-weight scaled) ----------------
__global__ __launch_bounds__(256) void moe_gemm2(const float* __restrict__ wd) {
    const int e = blockIdx.z;
    const int off = g_off[e];
    const int cnt = g_off[e + 1] - off;
    const int m0 = blockIdx.y * 128;
    if (m0 >= cnt) return;
    const int n0 = blockIdx.x * 64;

    __shared__ unsigned long long As2[16][128];
    __shared__ float Bs[16][64];

    const int tid = threadIdx.x;
    const int ar = tid >> 1, ak = (tid & 1) * 8;
    const int bk = tid >> 4, bn = (tid & 15) * 4;
    const int tr = (tid >> 3) * 4, tc = (tid & 7) * 8;

    int rrow = m0 + ar;
    if (rrow >= cnt) rrow = 0;
    const float* Aptr = g_hid + (size_t)(off + rrow) * FFD + ak;
    const float* Bptr = wd + (size_t)e * FFD * HIDDIM + (size_t)bk * HIDDIM + n0 + bn;

    unsigned long long acc[4][4];
#pragma unroll
    for (int i = 0; i < 4; i++)
#pragma unroll
        for (int j = 0; j < 4; j++) acc[i][j] = 0ull;

    for (int k0 = 0; k0 < FFD; k0 += 16) {
        float4 a0 = *(const float4*)(Aptr + k0);
        float4 a1 = *(const float4*)(Aptr + k0 + 4);
        As2[ak + 0][ar] = pk2(a0.x, a0.x);
        As2[ak + 1][ar] = pk2(a0.y, a0.y);
        As2[ak + 2][ar] = pk2(a0.z, a0.z);
        As2[ak + 3][ar] = pk2(a0.w, a0.w);
        As2[ak + 4][ar] = pk2(a1.x, a1.x);
        As2[ak + 5][ar] = pk2(a1.y, a1.y);
        As2[ak + 6][ar] = pk2(a1.z, a1.z);
        As2[ak + 7][ar] = pk2(a1.w, a1.w);
        *(float4*)&Bs[bk][bn] = *(const float4*)(Bptr + (size_t)k0 * HIDDIM);
        __syncthreads();
#pragma unroll
        for (int k = 0; k < 16; k++) {
            ulonglong2 a01 = *(const ulonglong2*)&As2[k][tr];
            ulonglong2 a23 = *(const ulonglong2*)&As2[k][tr + 2];
            const ulonglong2* bp = (const ulonglong2*)&Bs[k][tc];
            ulonglong2 b01 = bp[0], b23 = bp[1];
            fma2(acc[0][0], a01.x, b01.x); fma2(acc[0][1], a01.x, b01.y);
            fma2(acc[0][2], a01.x, b23.x); fma2(acc[0][3], a01.x, b23.y);
            fma2(acc[1][0], a01.y, b01.x); fma2(acc[1][1], a01.y, b01.y);
            fma2(acc[1][2], a01.y, b23.x); fma2(acc[1][3], a01.y, b23.y);
            fma2(acc[2][0], a23.x, b01.x); fma2(acc[2][1], a23.x, b01.y);
            fma2(acc[2][2], a23.x, b23.x); fma2(acc[2][3], a23.x, b23.y);
            fma2(acc[3][0], a23.y, b01.x); fma2(acc[3][1], a23.y, b01.y);
            fma2(acc[3][2], a23.y, b23.x); fma2(acc[3][3], a23.y, b23.y);
        }
        __syncthreads();
    }
#pragma unroll
    for (int i = 0; i < 4; i++) {
        int rr = m0 + tr + i;
        if (rr >= cnt) continue;
        float w = g_rows_w[off + rr];
        float2 u0 = upk2(acc[i][0]), u1 = upk2(acc[i][1]);
        float2 u2 = upk2(acc[i][2]), u3 = upk2(acc[i][3]);
        float* dst = &g_yex[(size_t)(off + rr) * HIDDIM + n0 + tc];
        *(float4*)dst = make_float4(u0.x * w, u0.y * w, u1.x * w, u1.y * w);
        *(float4*)(dst + 4) = make_float4(u2.x * w, u2.y * w, u3.x * w, u3.y * w);
    }
}

// ---------------- final combine ----------------
__global__ void combine_kernel(float* __restrict__ out) {
    int t = blockIdx.x;
    int r0 = g_tok_row[2 * t], r1 = g_tok_row[2 * t + 1];
    const float* hr = g_h + (size_t)t * HIDDIM;
    const float* y0 = g_yex + (size_t)r0 * HIDDIM;
    const float* y1 = g_yex + (size_t)r1 * HIDDIM;
    for (int d = threadIdx.x; d < HIDDIM; d += blockDim.x)
        out[(size_t)t * HIDDIM + d] = hr[d] + y0[d] + y1[d];
}

// ---------------- launch ----------------
extern "C" void kernel_launch(void* const* d_in, const int* in_sizes, int n_in,
                              void* d_out, int out_size) {
    const float* x    = (const float*)d_in[0];
    const float* n1w  = (const float*)d_in[1];
    const float* wqkv = (const float*)d_in[2];
    const float* wout = (const float*)d_in[3];
    const float* n2w  = (const float*)d_in[4];
    const float* wr   = (const float*)d_in[5];
    const float* wgu  = (const float*)d_in[6];
    const float* wd   = (const float*)d_in[7];
    float* out = (float*)d_out;

    void *p_xn, *p_qkv, *p_att, *p_h, *p_mi;
    cudaGetSymbolAddress(&p_xn, g_xn);
    cudaGetSymbolAddress(&p_qkv, g_qkv);
    cudaGetSymbolAddress(&p_att, g_att);
    cudaGetSymbolAddress(&p_h, g_h);
    cudaGetSymbolAddress(&p_mi, g_mi);

    // 1. pre-attention RMSNorm
    rmsnorm_kernel<<<SEQ, 256>>>(x, n1w, (float*)p_xn);

    // 2. QKV projection
    {
        dim3 grid(QKVC / 64, SEQ / 128);
        gemm_f2<false><<<grid, 256>>>((const float*)p_xn, wqkv, nullptr, (float*)p_qkv,
                                      SEQ, QKVC, HIDDIM);
    }

    // 3. RoPE on q and k
    rope_kernel<<<SEQ, 512>>>((float*)p_qkv);

    // 4. causal flash attention
    {
        dim3 grid(SEQ / 64, NQH);
        size_t smem = (size_t)(64 * 68 * 3 + 64 * 64 + 64 + 64 + 256 + 256) * sizeof(float);
        cudaFuncSetAttribute(attn_kernel, cudaFuncAttributeMaxDynamicSharedMemorySize, (int)smem);
        attn_kernel<<<grid, 256, smem>>>((const float*)p_qkv, (float*)p_att);
    }

    // 5. output projection + residual
    {
        dim3 grid(HIDDIM / 64, SEQ / 128);
        gemm_f2<true><<<grid, 256>>>((const float*)p_att, wout, x, (float*)p_h,
                                     SEQ, HIDDIM, HIDDIM);
    }

    // 6. pre-MoE RMSNorm
    rmsnorm_kernel<<<SEQ, 256>>>((const float*)p_h, n2w, (float*)p_mi);

    // 7. routing
    zero_cnt_kernel<<<1, 32>>>();
    router_kernel<<<SEQ, 128>>>((const float*)p_mi, wr);
    prefix_kernel<<<1, 1>>>();
    scatter_kernel<<<(SEQ + 255) / 256, 256>>>();

    // 8. expert gate/up GEMM + fused SiLU
    {
        dim3 grid(FFD / 64, NROWS / 128, NEXP);
        moe_gemm1<<<grid, 256>>>((const float*)p_mi, wgu);
    }

    // 9. expert down GEMM
    {
        dim3 grid(HIDDIM / 64, NROWS / 128, NEXP);
        moe_gemm2<<<grid, 256>>>(wd);
    }

    // 10. combine
    combine_kernel<<<SEQ, 256>>>(out);
}

// round 8
// speedup vs baseline: 2.3564x; 2.3564x over previous
#include <cuda_runtime.h>
#include <cuda_bf16.h>
#include <math.h>

#define SEQ 2048
#define HIDDIM 768
#define NQH 12
#define NKVH 3
#define HDIM 64
#define QKVC 1152        // (12 + 3 + 3) * 64
#define NEXP 16
#define FFD 1536
#define NROWS (SEQ * 2)  // top-2 assignments

// ---------------- f32x2 helpers (attention only — measured faster there) ----------------
__device__ __forceinline__ unsigned long long pk2(float x, float y) {
    unsigned long long r;
    asm("mov.b64 %0, {%1, %2};" : "=l"(r) : "f"(x), "f"(y));
    return r;
}
__device__ __forceinline__ float2 upk2(unsigned long long p) {
    float2 f;
    asm("mov.b64 {%0, %1}, %2;" : "=f"(f.x), "=f"(f.y) : "l"(p));
    return f;
}
__device__ __forceinline__ void fma2(unsigned long long& d, unsigned long long a, unsigned long long b) {
    asm("fma.rn.f32x2 %0, %1, %2, %0;" : "+l"(d) : "l"(a), "l"(b));
}
__device__ __forceinline__ unsigned long long mul2(unsigned long long a, unsigned long long b) {
    unsigned long long r;
    asm("mul.rn.f32x2 %0, %1, %2;" : "=l"(r) : "l"(a), "l"(b));
    return r;
}

// ---------------- tf32 mma helpers ----------------
__device__ __forceinline__ unsigned f2tf32(float f) {
    unsigned r;
    asm("cvt.rna.tf32.f32 %0, %1;" : "=r"(r) : "f"(f));
    return r;
}
__device__ __forceinline__ void mma_tf32(float* c, const unsigned* a, unsigned b0, unsigned b1) {
    asm("mma.sync.aligned.m16n8k8.row.col.f32.tf32.tf32.f32 "
        "{%0,%1,%2,%3}, {%4,%5,%6,%7}, {%8,%9}, {%0,%1,%2,%3};"
        : "+f"(c[0]), "+f"(c[1]), "+f"(c[2]), "+f"(c[3])
        : "r"(a[0]), "r"(a[1]), "r"(a[2]), "r"(a[3]), "r"(b0), "r"(b1));
}

// ---------------- device-global scratch ----------------
__device__ float g_xn [SEQ * HIDDIM];
__device__ float g_qkv[SEQ * QKVC];
__device__ float g_att[SEQ * HIDDIM];
__device__ float g_h  [SEQ * HIDDIM];
__device__ float g_mi [SEQ * HIDDIM];
__device__ int   g_eidx[SEQ * 2];
__device__ float g_ew  [SEQ * 2];
__device__ int   g_cnt[NEXP];
__device__ int   g_off[NEXP + 1];
__device__ int   g_cur[NEXP];
__device__ int   g_rows_tok[NROWS];
__device__ float g_rows_w [NROWS];
__device__ int   g_tok_row[SEQ * 2];
__device__ float g_gu [(size_t)NROWS * 2 * FFD];  // 50 MB gate|up
__device__ float g_hid[(size_t)NROWS * FFD];      // 25 MB
__device__ float g_yex[(size_t)NROWS * HIDDIM];   // 12.6 MB

// ---------------- RMSNorm ----------------
__global__ void rmsnorm_kernel(const float* __restrict__ x, const float* __restrict__ w,
                               float* __restrict__ out) {
    int t = blockIdx.x;
    __shared__ float red[256];
    const float* xr = x + (size_t)t * HIDDIM;
    float ss = 0.f;
    for (int i = threadIdx.x; i < HIDDIM; i += 256) { float v = xr[i]; ss += v * v; }
    red[threadIdx.x] = ss;
    __syncthreads();
    for (int s2 = 128; s2 > 0; s2 >>= 1) {
        if (threadIdx.x < s2) red[threadIdx.x] += red[threadIdx.x + s2];
        __syncthreads();
    }
    float inv = rsqrtf(red[0] * (1.0f / HIDDIM) + 1e-6f);
    for (int i = threadIdx.x; i < HIDDIM; i += 256)
        out[(size_t)t * HIDDIM + i] = xr[i] * inv * w[i];
}

// ---------------- tf32 tensor-core GEMM: CTA 128x128, 8 warps of 32x64 ----------------
// MODE 0: C = A@B            (qkv)
// MODE 1: C = A@B + Res      (out-proj + residual)
// MODE 2: moe1 — A rows gathered via g_rows_tok (per-expert), store guarded
// MODE 3: moe2 — A rows contiguous per expert, store scaled by g_rows_w, guarded
template <int MODE>
__global__ __launch_bounds__(256, 2) void gemm_mma(const float* __restrict__ A,
                                                   const float* __restrict__ B,
                                                   const float* __restrict__ Res,
                                                   float* __restrict__ C,
                                                   int M, int N, int K) {
    __shared__ unsigned As[128][36];   // stride 36 -> a-frag banks = 4g+t (conflict-free)
    __shared__ unsigned Bs[32][136];   // stride 136 -> b-frag banks = 8t+g (conflict-free)
    __shared__ int toks[128];

    int off = 0, cnt = M;
    const float* Bp = B;
    if (MODE >= 2) {
        int e = blockIdx.z;
        off = g_off[e];
        cnt = g_off[e + 1] - off;
        if ((int)blockIdx.y * 128 >= cnt) return;
        Bp = B + (size_t)e * K * N;
    }
    const int m0 = blockIdx.y * 128, n0 = blockIdx.x * 128;
    const int tid = threadIdx.x;

    if (MODE == 2) {
        if (tid < 128) {
            int rr = m0 + tid;
            toks[tid] = (rr < cnt) ? g_rows_tok[off + rr] : g_rows_tok[off];
        }
        __syncthreads();
    }

    // global->smem load assignments
    const int arow = tid >> 1, akk = (tid & 1) * 16;      // A: row, 16-float half
    const float* Aload;
    if (MODE == 2) {
        Aload = A + (size_t)toks[arow] * K + akk;
    } else if (MODE == 3) {
        int rr = m0 + arow; if (rr >= cnt) rr = 0;
        Aload = A + (size_t)(off + rr) * K + akk;
    } else {
        Aload = A + (size_t)(m0 + arow) * K + akk;
    }
    const int bkr = tid >> 3, bnc = (tid & 7) * 16;       // B: k row, 16-float slice
    const float* Bload = Bp + (size_t)bkr * N + n0 + bnc;

    const int wid = tid >> 5, lid = tid & 31;
    const int wm = (wid >> 1) * 32;   // 4 warps along M
    const int wn = (wid & 1) * 64;    // 2 warps along N
    const int g = lid >> 2, t = lid & 3;

    float acc[2][8][4];
#pragma unroll
    for (int mt = 0; mt < 2; mt++)
#pragma unroll
        for (int nt = 0; nt < 8; nt++)
#pragma unroll
            for (int i = 0; i < 4; i++) acc[mt][nt][i] = 0.f;

    for (int k0 = 0; k0 < K; k0 += 32) {
        const float* ap = Aload + k0;
#pragma unroll
        for (int i = 0; i < 4; i++) {
            float4 v = *(const float4*)(ap + i * 4);
            As[arow][akk + i * 4 + 0] = f2tf32(v.x);
            As[arow][akk + i * 4 + 1] = f2tf32(v.y);
            As[arow][akk + i * 4 + 2] = f2tf32(v.z);
            As[arow][akk + i * 4 + 3] = f2tf32(v.w);
        }
        const float* bp = Bload + (size_t)k0 * N;
#pragma unroll
        for (int i = 0; i < 4; i++) {
            float4 v = *(const float4*)(bp + i * 4);
            Bs[bkr][bnc + i * 4 + 0] = f2tf32(v.x);
            Bs[bkr][bnc + i * 4 + 1] = f2tf32(v.y);
            Bs[bkr][bnc + i * 4 + 2] = f2tf32(v.z);
            Bs[bkr][bnc + i * 4 + 3] = f2tf32(v.w);
        }
        __syncthreads();
#pragma unroll
        for (int s = 0; s < 4; s++) {
            const int ks = s * 8;
            unsigned a[2][4];
#pragma unroll
            for (int mt = 0; mt < 2; mt++) {
                const int rb = wm + mt * 16;
                a[mt][0] = As[rb + g][ks + t];
                a[mt][1] = As[rb + g + 8][ks + t];
                a[mt][2] = As[rb + g][ks + t + 4];
                a[mt][3] = As[rb + g + 8][ks + t + 4];
            }
#pragma unroll
            for (int nt = 0; nt < 8; nt++) {
                unsigned b0 = Bs[ks + t][wn + nt * 8 + g];
                unsigned b1 = Bs[ks + t + 4][wn + nt * 8 + g];
                mma_tf32(acc[0][nt], a[0], b0, b1);
                mma_tf32(acc[1][nt], a[1], b0, b1);
            }
        }
        __syncthreads();
    }

    // epilogue
#pragma unroll
    for (int mt = 0; mt < 2; mt++) {
        const int lr0 = wm + mt * 16 + g;
        const int lr1 = lr0 + 8;
        if (MODE <= 1) {
            const size_t r0 = (size_t)(m0 + lr0) * N;
            const size_t r1 = (size_t)(m0 + lr1) * N;
#pragma unroll
            for (int nt = 0; nt < 8; nt++) {
                const int col = n0 + wn + nt * 8 + 2 * t;
                float2 v0 = make_float2(acc[mt][nt][0], acc[mt][nt][1]);
                float2 v1 = make_float2(acc[mt][nt][2], acc[mt][nt][3]);
                if (MODE == 1) {
                    float2 q0 = *(const float2*)&Res[r0 + col];
                    float2 q1 = *(const float2*)&Res[r1 + col];
                    v0.x += q0.x; v0.y += q0.y; v1.x += q1.x; v1.y += q1.y;
                }
                *(float2*)&C[r0 + col] = v0;
                *(float2*)&C[r1 + col] = v1;
            }
        } else {
            const int rr0 = m0 + lr0, rr1 = m0 + lr1;
            const bool s0 = rr0 < cnt, s1 = rr1 < cnt;
            float w0 = 1.f, w1 = 1.f;
            if (MODE == 3) {
                if (s0) w0 = g_rows_w[off + rr0];
                if (s1) w1 = g_rows_w[off + rr1];
            }
            const size_t r0 = (size_t)(off + rr0) * N;
            const size_t r1 = (size_t)(off + rr1) * N;
#pragma unroll
            for (int nt = 0; nt < 8; nt++) {
                const int col = n0 + wn + nt * 8 + 2 * t;
                if (s0) {
                    float2 v = make_float2(acc[mt][nt][0] * w0, acc[mt][nt][1] * w0);
                    *(float2*)&C[r0 + col] = v;
                }
                if (s1) {
                    float2 v = make_float2(acc[mt][nt][2] * w1, acc[mt][nt][3] * w1);
                    *(float2*)&C[r1 + col] = v;
                }
            }
        }
    }
}

// ---------------- SiLU(gate)*up from g_gu -> g_hid ----------------
__global__ void silu_kernel() {
    int i = blockIdx.x * blockDim.x + threadIdx.x;          // float4 index
    const int TOT = NROWS * (FFD / 4);
    if (i >= TOT) return;
    int r = i / (FFD / 4);
    int c4 = i % (FFD / 4);
    const float4* base = (const float4*)g_gu + (size_t)r * (2 * FFD / 4);
    float4 gv = base[c4];
    float4 uv = base[FFD / 4 + c4];
    float4 o;
    o.x = gv.x / (1.f + __expf(-gv.x)) * uv.x;
    o.y = gv.y / (1.f + __expf(-gv.y)) * uv.y;
    o.z = gv.z / (1.f + __expf(-gv.z)) * uv.z;
    o.w = gv.w / (1.f + __expf(-gv.w)) * uv.w;
    ((float4*)g_hid)[i] = o;
}

// ---------------- RoPE ----------------
__global__ void rope_kernel(float* __restrict__ qkv) {
    int s = blockIdx.x;
    int t = threadIdx.x;
    if (t >= (NQH + NKVH) * (HDIM / 2)) return;
    int hh = t / 32, p = t & 31;
    int col = (hh < NQH) ? hh * HDIM : (NQH * HDIM + (hh - NQH) * HDIM);
    float expo = (float)(2 * p) * (1.0f / HDIM);
    float inv = powf(10000.0f, -expo);
    float ang = (float)s * inv;
    float c, sn;
    sincosf(ang, &sn, &c);
    float* base = qkv + (size_t)s * QKVC + col;
    float x0 = base[2 * p], x1 = base[2 * p + 1];
    base[2 * p]     = x0 * c - x1 * sn;
    base[2 * p + 1] = x0 * sn + x1 * c;
}

// ---------------- causal flash attention (fp32, f32x2 inner loops) ----------------
__global__ __launch_bounds__(256) void attn_kernel(const float* __restrict__ qkv,
                                                   float* __restrict__ out) {
    extern __shared__ float sm[];
    float* QsT  = sm;                  // [64][68]
    float* Kst  = QsT + 64 * 68;       // [64][68]
    float* Vs   = Kst + 64 * 68;       // [64][64]
    float* Ss   = Vs + 64 * 64;        // [64][68]
    float* rowM = Ss + 64 * 68;
    float* rowL = rowM + 64;
    float* partM = rowL + 64;          // [4][64]
    float* partL = partM + 256;        // [4][64]

    const int h = blockIdx.y, kvh = h >> 2;
    const int qt = gridDim.x - 1 - blockIdx.x;   // heavy tiles first
    const int q0 = qt * 64;
    const int tid = threadIdx.x;
    const int r = tid & 63;
    const int cg = tid >> 6;

    unsigned long long op[8];
#pragma unroll
    for (int j = 0; j < 8; j++) op[j] = 0ull;

    for (int i = tid; i < 4096; i += 256) {
        int m = i >> 6, d = i & 63;
        QsT[d * 68 + m] = qkv[(size_t)(q0 + m) * QKVC + h * HDIM + d] * 0.125f;
    }
    if (tid < 64) { rowM[tid] = -1e30f; rowL[tid] = 0.f; }
    __syncthreads();

    for (int kt = 0; kt <= qt; ++kt) {
        const int k0 = kt * 64;
        for (int i = tid; i < 4096; i += 256) {
            int c = i >> 6, d = i & 63;
            const float* row = qkv + (size_t)(k0 + c) * QKVC;
            Kst[d * 68 + c] = row[NQH * HDIM + kvh * HDIM + d];
            Vs[c * 64 + d]  = row[(NQH + NKVH) * HDIM + kvh * HDIM + d];
        }
        __syncthreads();

        unsigned long long sp[8];
#pragma unroll
        for (int j = 0; j < 8; j++) sp[j] = 0ull;
#pragma unroll 4
        for (int d = 0; d < 64; ++d) {
            unsigned long long qq;
            {
                float qv = QsT[d * 68 + r];
                qq = pk2(qv, qv);
            }
            const ulonglong2* kp = (const ulonglong2*)&Kst[d * 68 + cg * 16];
            ulonglong2 ka = kp[0], kb = kp[1], kc = kp[2], kd = kp[3];
            fma2(sp[0], qq, ka.x); fma2(sp[1], qq, ka.y);
            fma2(sp[2], qq, kb.x); fma2(sp[3], qq, kb.y);
            fma2(sp[4], qq, kc.x); fma2(sp[5], qq, kc.y);
            fma2(sp[6], qq, kd.x); fma2(sp[7], qq, kd.y);
        }

        float s[16];
#pragma unroll
        for (int j = 0; j < 8; j++) {
            float2 u = upk2(sp[j]);
            s[2 * j] = u.x; s[2 * j + 1] = u.y;
        }

        bool diag = (kt == qt);
        float lmax = -1e30f;
#pragma unroll
        for (int j = 0; j < 16; j++) {
            int c = cg * 16 + j;
            if (diag && (k0 + c > q0 + r)) s[j] = -1e30f;
            lmax = fmaxf(lmax, s[j]);
        }
        partM[cg * 64 + r] = lmax;
        __syncthreads();

        float m_old = rowM[r];
        float m_new = fmaxf(m_old,
                      fmaxf(fmaxf(partM[r], partM[64 + r]),
                            fmaxf(partM[128 + r], partM[192 + r])));
        float alpha = __expf(m_old - m_new);
        float lsum = 0.f;
#pragma unroll
        for (int j = 0; j < 16; j++) {
            float p = __expf(s[j] - m_new);
            Ss[r * 68 + cg * 16 + j] = p;
            lsum += p;
        }
        partL[cg * 64 + r] = lsum;
        {
            unsigned long long aa = pk2(alpha, alpha);
#pragma unroll
            for (int j = 0; j < 8; j++) op[j] = mul2(op[j], aa);
        }
        __syncthreads();

        if (cg == 0) {
            rowM[r] = m_new;
            rowL[r] = rowL[r] * alpha + partL[r] + partL[64 + r] + partL[128 + r] + partL[192 + r];
        }

#pragma unroll 4
        for (int c = 0; c < 64; c++) {
            unsigned long long pp;
            {
                float pv = Ss[r * 68 + c];
                pp = pk2(pv, pv);
            }
            const ulonglong2* vp = (const ulonglong2*)&Vs[c * 64 + cg * 16];
            ulonglong2 va = vp[0], vb = vp[1], vc = vp[2], vd = vp[3];
            fma2(op[0], pp, va.x); fma2(op[1], pp, va.y);
            fma2(op[2], pp, vb.x); fma2(op[3], pp, vb.y);
            fma2(op[4], pp, vc.x); fma2(op[5], pp, vc.y);
            fma2(op[6], pp, vd.x); fma2(op[7], pp, vd.y);
        }
        __syncthreads();
    }

    float inv = 1.f / rowL[r];
    float* orow = out + (size_t)(q0 + r) * (NQH * HDIM) + h * HDIM + cg * 16;
#pragma unroll
    for (int j = 0; j < 8; j++) {
        float2 u = upk2(op[j]);
        orow[2 * j]     = u.x * inv;
        orow[2 * j + 1] = u.y * inv;
    }
}

// ---------------- router ----------------
__global__ void router_kernel(const float* __restrict__ x, const float* __restrict__ wr) {
    int t = blockIdx.x;
    __shared__ float xr[HIDDIM];
    __shared__ float lg[NEXP];
    for (int i = threadIdx.x; i < HIDDIM; i += blockDim.x) xr[i] = x[(size_t)t * HIDDIM + i];
    __syncthreads();
    if (threadIdx.x < NEXP) {
        float a = 0.f;
        for (int k = 0; k < HIDDIM; k++) a += xr[k] * wr[k * NEXP + threadIdx.x];
        lg[threadIdx.x] = a;
    }
    __syncthreads();
    if (threadIdx.x == 0) {
        int i0 = 0; float l0 = lg[0];
        for (int e = 1; e < NEXP; e++) if (lg[e] > l0) { l0 = lg[e]; i0 = e; }
        int i1 = (i0 == 0) ? 1 : 0; float l1 = lg[i1];
        for (int e = 0; e < NEXP; e++) if (e != i0 && lg[e] > l1) { l1 = lg[e]; i1 = e; }
        float w0 = 1.f / (1.f + __expf(l1 - l0));
        g_eidx[2 * t] = i0; g_eidx[2 * t + 1] = i1;
        g_ew[2 * t] = w0;   g_ew[2 * t + 1] = 1.f - w0;
        atomicAdd(&g_cnt[i0], 1);
        atomicAdd(&g_cnt[i1], 1);
    }
}

__global__ void zero_cnt_kernel() { if (threadIdx.x < NEXP) g_cnt[threadIdx.x] = 0; }

__global__ void prefix_kernel() {
    if (threadIdx.x == 0) {
        int acc = 0;
        for (int e = 0; e < NEXP; e++) { g_off[e] = acc; g_cur[e] = acc; acc += g_cnt[e]; }
        g_off[NEXP] = acc;
    }
}

__global__ void scatter_kernel() {
    int t = blockIdx.x * blockDim.x + threadIdx.x;
    if (t >= SEQ) return;
    for (int j = 0; j < 2; j++) {
        int e = g_eidx[2 * t + j];
        int pos = atomicAdd(&g_cur[e], 1);
        g_rows_tok[pos] = t;
        g_rows_w[pos] = g_ew[2 * t + j];
        g_tok_row[2 * t + j] = pos;
    }
}

// ---------------- final combine ----------------
__global__ void combine_kernel(float* __restrict__ out) {
    int t = blockIdx.x;
    int r0 = g_tok_row[2 * t], r1 = g_tok_row[2 * t + 1];
    const float* hr = g_h + (size_t)t * HIDDIM;
    const float* y0 = g_yex + (size_t)r0 * HIDDIM;
    const float* y1 = g_yex + (size_t)r1 * HIDDIM;
    for (int d = threadIdx.x; d < HIDDIM; d += blockDim.x)
        out[(size_t)t * HIDDIM + d] = hr[d] + y0[d] + y1[d];
}

// ---------------- launch ----------------
extern "C" void kernel_launch(void* const* d_in, const int* in_sizes, int n_in,
                              void* d_out, int out_size) {
    const float* x    = (const float*)d_in[0];
    const float* n1w  = (const float*)d_in[1];
    const float* wqkv = (const float*)d_in[2];
    const float* wout = (const float*)d_in[3];
    const float* n2w  = (const float*)d_in[4];
    const float* wr   = (const float*)d_in[5];
    const float* wgu  = (const float*)d_in[6];
    const float* wd   = (const float*)d_in[7];
    float* out = (float*)d_out;

    void *p_xn, *p_qkv, *p_att, *p_h, *p_mi, *p_gu, *p_hid, *p_yex;
    cudaGetSymbolAddress(&p_xn, g_xn);
    cudaGetSymbolAddress(&p_qkv, g_qkv);
    cudaGetSymbolAddress(&p_att, g_att);
    cudaGetSymbolAddress(&p_h, g_h);
    cudaGetSymbolAddress(&p_mi, g_mi);
    cudaGetSymbolAddress(&p_gu, g_gu);
    cudaGetSymbolAddress(&p_hid, g_hid);
    cudaGetSymbolAddress(&p_yex, g_yex);

    // 1. pre-attention RMSNorm
    rmsnorm_kernel<<<SEQ, 256>>>(x, n1w, (float*)p_xn);

    // 2. QKV projection (tf32 mma)
    {
        dim3 grid(QKVC / 128, SEQ / 128);
        gemm_mma<0><<<grid, 256>>>((const float*)p_xn, wqkv, nullptr, (float*)p_qkv,
                                   SEQ, QKVC, HIDDIM);
    }

    // 3. RoPE on q and k
    rope_kernel<<<SEQ, 512>>>((float*)p_qkv);

    // 4. causal flash attention
    {
        dim3 grid(SEQ / 64, NQH);
        size_t smem = (size_t)(64 * 68 * 3 + 64 * 64 + 64 + 64 + 256 + 256) * sizeof(float);
        cudaFuncSetAttribute(attn_kernel, cudaFuncAttributeMaxDynamicSharedMemorySize, (int)smem);
        attn_kernel<<<grid, 256, smem>>>((const float*)p_qkv, (float*)p_att);
    }

    // 5. output projection + residual (tf32 mma)
    {
        dim3 grid(HIDDIM / 128, SEQ / 128);
        gemm_mma<1><<<grid, 256>>>((const float*)p_att, wout, x, (float*)p_h,
                                   SEQ, HIDDIM, NQH * HDIM);
    }

    // 6. pre-MoE RMSNorm
    rmsnorm_kernel<<<SEQ, 256>>>((const float*)p_h, n2w, (float*)p_mi);

    // 7. routing
    zero_cnt_kernel<<<1, 32>>>();
    router_kernel<<<SEQ, 128>>>((const float*)p_mi, wr);
    prefix_kernel<<<1, 1>>>();
    scatter_kernel<<<(SEQ + 255) / 256, 256>>>();

    // 8. expert gate/up GEMM (tf32 mma, gathered rows) -> g_gu
    {
        dim3 grid((2 * FFD) / 128, NROWS / 128, NEXP);
        gemm_mma<2><<<grid, 256>>>((const float*)p_mi, wgu, nullptr, (float*)p_gu,
                                   NROWS, 2 * FFD, HIDDIM);
    }

    // 8b. SiLU(gate) * up -> g_hid
    {
        int tot = NROWS * (FFD / 4);
        silu_kernel<<<(tot + 255) / 256, 256>>>();
    }

    // 9. expert down GEMM (tf32 mma, combine-weight scaled) -> g_yex
    {
        dim3 grid(HIDDIM / 128, NROWS / 128, NEXP);
        gemm_mma<3><<<grid, 256>>>((const float*)p_hid, wd, nullptr, (float*)p_yex,
                                   NROWS, HIDDIM, FFD);
    }

    // 10. combine
    combine_kernel<<<SEQ, 256>>>(out);
}